// round 6
// baseline (speedup 1.0000x reference)
#include <cuda_runtime.h>
#include <math.h>

#define DEVHOST __host__ __device__
typedef unsigned long long u64;

// ------------------------- compile-time structure -------------------------
DEVHOST constexpr int kTL (int i){ const int a[23]={0,0,0,0, 1,1,1,1,1,1, 2,2,2,2,2,2,2, 3,3,3,3,3,3}; return a[i]; }
DEVHOST constexpr int kTL1(int i){ const int a[23]={0,1,2,3, 1,1,2,2,3,3, 1,2,2,2,3,3,3, 2,2,3,3,3,3}; return a[i]; }
DEVHOST constexpr int kTL2(int i){ const int a[23]={0,1,2,3, 0,1,1,2,2,3, 1,0,1,2,1,2,3, 1,2,0,1,2,3}; return a[i]; }

DEVHOST constexpr int imax2(int a,int b){ return a>b?a:b; }
DEVHOST constexpr int imin2(int a,int b){ return a<b?a:b; }
DEVHOST constexpr int ilo_c(int l1,int l2,int m){ return imax2(-l1, m-l2); }
DEVHOST constexpr int ihi_c(int l1,int l2,int m){ return imin2( l1, m+l2); }
DEVHOST constexpr int rown_c(int l1,int l2,int m){ return ihi_c(l1,l2,m)-ilo_c(l1,l2,m)+1; }

DEVHOST constexpr int  kInOff(int l){ const int  a[4]={0,16,64,144};                       return a[l]; }
DEVHOST constexpr int  kMLf  (int l){ const int  a[4]={1024,1536,1792,1536};               return a[l]; }
DEVHOST constexpr long kMidBase(int l){ const long a[4]={0L,2097152L,11534336L,29884416L}; return a[l]; }
DEVHOST constexpr int  kTrip0(int l){ const int  a[4]={0,4,10,17};                         return a[l]; }
DEVHOST constexpr int  kSOff (int l){ const int  a[4]={0,1024,2560,4352};                  return a[l]; }
DEVHOST constexpr int  kWBase(int l){ const int  a[4]={0,16384,40960,69632};               return a[l]; }

// ------------------- compile-time Clebsch-Gordan values -------------------
DEVHOST constexpr double dfact(int n){ double r=1.0; for(int i=2;i<=n;++i) r*=(double)i; return r; }
DEVHOST constexpr double csqrt(double x){
    double g = (x>1.0)?x:1.0;
    for(int i=0;i<64;++i) g = 0.5*(g + x/g);
    return g;
}
DEVHOST constexpr double cgcoef(int l1,int m1,int l2,int m2,int l,int m){
    double pre = csqrt((double)(2*l+1)*dfact(l1+l2-l)*dfact(l1-l2+l)*dfact(-l1+l2+l)/dfact(l1+l2+l+1));
    pre = pre * csqrt(dfact(l+m)*dfact(l-m)*dfact(l1-m1)*dfact(l1+m1)*dfact(l2-m2)*dfact(l2+m2));
    double s = 0.0;
    for(int k=0;k<=l1+l2-l;++k){
        int d0=k, d1=l1+l2-l-k, d2=l1-m1-k, d3=l2+m2-k, d4=l-l2+m1+k, d5=l-l1-m2+k;
        if(d0<0||d1<0||d2<0||d3<0||d4<0||d5<0) continue;
        double den = dfact(d0)*dfact(d1)*dfact(d2)*dfact(d3)*dfact(d4)*dfact(d5);
        s += ((k&1)? -1.0 : 1.0)/den;
    }
    return pre*s;
}

// ------------------------------ device scratch ----------------------------
static constexpr int  NCH       = 5888;
static constexpr int  NBLK1     = 256;
static constexpr long MID_TOTAL = 51904512L;

__device__ float  g_part[(long)NBLK1 * NCH];
__device__ float  g_scale[NCH];
__device__ float2 g_wsc[94208];
__device__ float2 g_mid[MID_TOTAL];

// -------------------------------- f32x2 ops -------------------------------
__device__ __forceinline__ u64 pk2(float lo, float hi){
    u64 r; asm("mov.b64 %0,{%1,%2};" : "=l"(r) : "f"(lo), "f"(hi)); return r;
}
__device__ __forceinline__ void upk2(float& lo, float& hi, u64 v){
    asm("mov.b64 {%0,%1},%2;" : "=f"(lo), "=f"(hi) : "l"(v));
}
__device__ __forceinline__ u64 fma2(u64 a, u64 b, u64 c){
    u64 d; asm("fma.rn.f32x2 %0,%1,%2,%3;" : "=l"(d) : "l"(a), "l"(b), "l"(c)); return d;
}
__device__ __forceinline__ u64 add2(u64 a, u64 b){
    u64 d; asm("add.rn.f32x2 %0,%1,%2;" : "=l"(d) : "l"(a), "l"(b)); return d;
}

// --------------------- k1: tensor product + |mid|^2 partials --------------
template<int TR,int P,int J,int N,int D1,int D2>
struct JL {
    static __device__ __forceinline__ void run(const float2 (&f1)[D1], const float2 (&f2)[D2],
                                               float& ar, float& ai){
        constexpr int L=kTL(TR), L1=kTL1(TR), L2=kTL2(TR);
        constexpr int M  = P - L;
        constexpr int M1 = ilo_c(L1,L2,M) + J;
        constexpr int M2 = M - M1;
        constexpr float v = (float)cgcoef(L1,M1,L2,M2,L,M);
        float2 a = f1[M1+L1];
        float2 b = f2[M2+L2];
        ar += v*(a.x*b.x - a.y*b.y);
        ai += v*(a.x*b.y + a.y*b.x);
        if constexpr (J+1 < N) JL<TR,P,J+1,N,D1,D2>::run(f1,f2,ar,ai);
    }
};

template<int TR,int P,int D1,int D2>
struct PL {
    static __device__ __forceinline__ void run(const float2 (&f1)[D1], const float2 (&f2)[D2],
                                               float2* op, float& nsq){
        constexpr int L = kTL(TR);
        constexpr int N = rown_c(kTL1(TR),kTL2(TR),P-L);
        float ar=0.f, ai=0.f;
        JL<TR,P,0,N,D1,D2>::run(f1,f2,ar,ai);
        op[P] = make_float2(ar,ai);
        nsq += ar*ar + ai*ai;
        if constexpr (P+1 < 2*L+1) PL<TR,P+1,D1,D2>::run(f1,f2,op,nsq);
    }
};

template<int TR>
__device__ __forceinline__ void do_trip(const float* sF, int t, int s, int tid, int b0){
    constexpr int  L  = kTL(TR), L1 = kTL1(TR), L2 = kTL2(TR);
    constexpr int  D1 = 2*L1+1, D2 = 2*L2+1;
    constexpr int  ML = kMLf(L);
    constexpr long MB = kMidBase(L);
    const int cl = (TR - kTrip0(L))*256 + tid;
    float nsq = 0.f;
    for (int bs=0; bs<8; ++bs){
        const float2* fb = reinterpret_cast<const float2*>(sF + bs*512);
        float2 f1[D1], f2[D2];
        #pragma unroll
        for (int i=0;i<D1;++i) f1[i] = fb[kInOff(L1) + t*D1 + i];
        #pragma unroll
        for (int i=0;i<D2;++i) f2[i] = fb[kInOff(L2) + s*D2 + i];
        float2* op = g_mid + MB + (long)((b0+bs)*ML + cl)*(2*L+1);
        PL<TR,0,D1,D2>::run(f1,f2,op,nsq);
    }
    g_part[(long)blockIdx.x*NCH + TR*256 + tid] = nsq;
}

template<int TR>
struct TripsAll {
    static __device__ __forceinline__ void run(const float* sF, int t, int s, int tid, int b0){
        do_trip<TR>(sF,t,s,tid,b0);
        if constexpr (TR+1 < 23) TripsAll<TR+1>::run(sF,t,s,tid,b0);
    }
};

__global__ void __launch_bounds__(256) k1_kernel(const float* __restrict__ act){
    __shared__ float sF[8*512];
    const int tid = threadIdx.x;
    const int b0  = blockIdx.x*8;
    const float4* src = reinterpret_cast<const float4*>(act + (long)b0*512);
    float4* dst = reinterpret_cast<float4*>(sF);
    for (int i=tid; i<1024; i+=256) dst[i] = src[i];
    __syncthreads();
    TripsAll<0>::run(sF, tid>>4, tid&15, tid, b0);
}

// ------------- k2a: reduce partials -> inverse (new_std + eps) ------------
__global__ void k2a_kernel(const float* __restrict__ bn){
    int c = blockIdx.x*256 + threadIdx.x;
    if (c >= NCH) return;
    int l = (c<1024)?0:((c<2560)?1:((c<4352)?2:3));
    float s = 0.f;
    for (int i=0;i<NBLK1;++i) s += g_part[(long)i*NCH + c];
    float bstd = sqrtf(s / (2048.0f * (float)(2*l+1)));
    g_scale[c] = 1.0f/(0.5f*(bn[c] + bstd) + 1e-5f);
}

// --------------------- k2b: fold scale into W ------------------------------
__global__ void k2b_kernel(const float* __restrict__ W){
    int r = blockIdx.x*256 + threadIdx.x;
    if (r >= 94208) return;
    int l = (r<16384)?0:((r<40960)?1:((r<69632)?2:3));
    int rr = r - kWBase(l);
    int c  = rr % kMLf(l);
    float sc = g_scale[kSOff(l) + c];
    g_wsc[r] = make_float2(W[2*r]*sc, W[2*r+1]*sc);
}

// -------- k3: out[b,o,p] = sum_c Wsc[o,c]*mid[b,c,p]  (complex, f32x2) -----
// 256 threads = 8 c-split x 8 o-groups(2o) x 4 b-groups(2b); block = 8 batches
template<int L>
__global__ void __launch_bounds__(256) k3_kernel(float* __restrict__ out){
    constexpr int  DP   = 2*L+1;
    constexpr int  ML   = kMLf(L);
    constexpr long MB   = kMidBase(L);
    constexpr int  WB   = kWBase(L);
    constexpr int  OROW = kInOff(L);

    const int tid = threadIdx.x;
    const int cs  = tid & 7;
    const int og  = (tid>>3) & 7;
    const int bg  = tid >> 6;
    const int o0  = og*2;
    const int b0  = blockIdx.x*8 + bg*2;

    u64 acc[2][2][DP];
    #pragma unroll
    for (int bi=0;bi<2;++bi)
        #pragma unroll
        for (int oi=0;oi<2;++oi)
            #pragma unroll
            for (int p=0;p<DP;++p) acc[bi][oi][p] = 0ULL;

    const float2* wp0 = g_wsc + WB + (long)o0*ML;
    const float2* wp1 = wp0 + ML;
    const float2* mb0 = g_mid + MB + (long)b0*ML*DP;
    const float2* mb1 = mb0 + (long)ML*DP;

    for (int c=cs; c<ML; c+=8){
        float2 w0 = __ldg(wp0 + c);
        float2 w1 = __ldg(wp1 + c);
        u64 wxx0 = pk2(w0.x, w0.x), wyy0 = pk2(-w0.y, w0.y);
        u64 wxx1 = pk2(w1.x, w1.x), wyy1 = pk2(-w1.y, w1.y);
        #pragma unroll
        for (int bi=0;bi<2;++bi){
            const float2* mp = (bi ? mb1 : mb0) + (long)c*DP;
            #pragma unroll
            for (int p=0;p<DP;++p){
                float2 m = __ldg(mp + p);
                u64 mxy = pk2(m.x, m.y);
                u64 myx = pk2(m.y, m.x);
                acc[bi][0][p] = fma2(wxx0, mxy, acc[bi][0][p]);
                acc[bi][0][p] = fma2(wyy0, myx, acc[bi][0][p]);
                acc[bi][1][p] = fma2(wxx1, mxy, acc[bi][1][p]);
                acc[bi][1][p] = fma2(wyy1, myx, acc[bi][1][p]);
            }
        }
    }

    // reduce over cs (lane bits 0..2) — deterministic butterfly
    #pragma unroll
    for (int bi=0;bi<2;++bi)
        #pragma unroll
        for (int oi=0;oi<2;++oi)
            #pragma unroll
            for (int p=0;p<DP;++p){
                u64 v = acc[bi][oi][p];
                v = add2(v, __shfl_xor_sync(0xffffffffu, v, 1));
                v = add2(v, __shfl_xor_sync(0xffffffffu, v, 2));
                v = add2(v, __shfl_xor_sync(0xffffffffu, v, 4));
                acc[bi][oi][p] = v;
            }

    if (cs == 0){
        #pragma unroll
        for (int bi=0;bi<2;++bi)
            #pragma unroll
            for (int oi=0;oi<2;++oi)
                #pragma unroll
                for (int p=0;p<DP;++p){
                    float x,y; upk2(x,y,acc[bi][oi][p]);
                    long row = (long)(b0+bi)*256 + OROW + (o0+oi)*DP + p;
                    reinterpret_cast<float2*>(out)[row] = make_float2(x,y);
                }
    }
}

// --------------------------------- launch ---------------------------------
extern "C" void kernel_launch(void* const* d_in, const int* in_sizes, int n_in,
                              void* d_out, int out_size){
    const float* act = nullptr;
    const float* W   = nullptr;
    const float* bn  = nullptr;
    for (int i=0;i<n_in;++i){
        if      (in_sizes[i] == 1048576) act = (const float*)d_in[i];
        else if (in_sizes[i] == 188416)  W   = (const float*)d_in[i];
        else if (in_sizes[i] == 5888)    bn  = (const float*)d_in[i];
    }
    float* out = (float*)d_out;

    k1_kernel<<<256,256>>>(act);
    k2a_kernel<<<23,256>>>(bn);
    k2b_kernel<<<368,256>>>(W);
    k3_kernel<0><<<256,256>>>(out);
    k3_kernel<1><<<256,256>>>(out);
    k3_kernel<2><<<256,256>>>(out);
    k3_kernel<3><<<256,256>>>(out);
}

// round 8
// speedup vs baseline: 1.3820x; 1.3820x over previous
#include <cuda_runtime.h>
#include <math.h>

#define DEVHOST __host__ __device__
typedef unsigned long long u64;

// ------------------------- compile-time structure -------------------------
DEVHOST constexpr int kTL (int i){ const int a[23]={0,0,0,0, 1,1,1,1,1,1, 2,2,2,2,2,2,2, 3,3,3,3,3,3}; return a[i]; }
DEVHOST constexpr int kTL1(int i){ const int a[23]={0,1,2,3, 1,1,2,2,3,3, 1,2,2,2,3,3,3, 2,2,3,3,3,3}; return a[i]; }
DEVHOST constexpr int kTL2(int i){ const int a[23]={0,1,2,3, 0,1,1,2,2,3, 1,0,1,2,1,2,3, 1,2,0,1,2,3}; return a[i]; }

DEVHOST constexpr int imax2(int a,int b){ return a>b?a:b; }
DEVHOST constexpr int imin2(int a,int b){ return a<b?a:b; }
DEVHOST constexpr int ilo_c(int l1,int l2,int m){ return imax2(-l1, m-l2); }
DEVHOST constexpr int ihi_c(int l1,int l2,int m){ return imin2( l1, m+l2); }
DEVHOST constexpr int rown_c(int l1,int l2,int m){ return ihi_c(l1,l2,m)-ilo_c(l1,l2,m)+1; }

DEVHOST constexpr int  kInOff(int l){ const int  a[4]={0,16,64,144};                       return a[l]; }
DEVHOST constexpr int  kMLf  (int l){ const int  a[4]={1024,1536,1792,1536};               return a[l]; }
DEVHOST constexpr long kMidBase(int l){ const long a[4]={0L,2097152L,11534336L,29884416L}; return a[l]; }
DEVHOST constexpr int  kTrip0(int l){ const int  a[4]={0,4,10,17};                         return a[l]; }
DEVHOST constexpr int  kSOff (int l){ const int  a[4]={0,1024,2560,4352};                  return a[l]; }
DEVHOST constexpr int  kWBase(int l){ const int  a[4]={0,16384,40960,69632};               return a[l]; }

// ------------------- compile-time Clebsch-Gordan values -------------------
DEVHOST constexpr double dfact(int n){ double r=1.0; for(int i=2;i<=n;++i) r*=(double)i; return r; }
DEVHOST constexpr double csqrt(double x){
    double g = (x>1.0)?x:1.0;
    for(int i=0;i<64;++i) g = 0.5*(g + x/g);
    return g;
}
DEVHOST constexpr double cgcoef(int l1,int m1,int l2,int m2,int l,int m){
    double pre = csqrt((double)(2*l+1)*dfact(l1+l2-l)*dfact(l1-l2+l)*dfact(-l1+l2+l)/dfact(l1+l2+l+1));
    pre = pre * csqrt(dfact(l+m)*dfact(l-m)*dfact(l1-m1)*dfact(l1+m1)*dfact(l2-m2)*dfact(l2+m2));
    double s = 0.0;
    for(int k=0;k<=l1+l2-l;++k){
        int d0=k, d1=l1+l2-l-k, d2=l1-m1-k, d3=l2+m2-k, d4=l-l2+m1+k, d5=l-l1-m2+k;
        if(d0<0||d1<0||d2<0||d3<0||d4<0||d5<0) continue;
        double den = dfact(d0)*dfact(d1)*dfact(d2)*dfact(d3)*dfact(d4)*dfact(d5);
        s += ((k&1)? -1.0 : 1.0)/den;
    }
    return pre*s;
}

// ------------------------------ device scratch ----------------------------
static constexpr int  NCH       = 5888;
static constexpr int  NBLK1     = 512;
static constexpr long MID_TOTAL = 51904512L;

__device__ float  g_part[(long)NBLK1 * NCH];
__device__ float  g_scale[NCH];
__device__ u64    g_wrr[94208];
__device__ u64    g_wii[94208];
__device__ float2 g_mid[MID_TOTAL];   // layout per l: [b][p][c]

// -------------------------------- f32x2 ops -------------------------------
__device__ __forceinline__ u64 pk2(float lo, float hi){
    u64 r; asm("mov.b64 %0,{%1,%2};" : "=l"(r) : "f"(lo), "f"(hi)); return r;
}
__device__ __forceinline__ void upk2(float& lo, float& hi, u64 v){
    asm("mov.b64 {%0,%1},%2;" : "=f"(lo), "=f"(hi) : "l"(v));
}
__device__ __forceinline__ u64 fma2(u64 a, u64 b, u64 c){
    u64 d; asm("fma.rn.f32x2 %0,%1,%2,%3;" : "=l"(d) : "l"(a), "l"(b), "l"(c)); return d;
}
__device__ __forceinline__ u64 add2(u64 a, u64 b){
    u64 d; asm("add.rn.f32x2 %0,%1,%2;" : "=l"(d) : "l"(a), "l"(b)); return d;
}
__device__ __forceinline__ ulonglong2 ldg2(const u64* p){
    ulonglong2 v;
    asm("ld.global.nc.v2.u64 {%0,%1},[%2];" : "=l"(v.x), "=l"(v.y) : "l"(p));
    return v;
}
__device__ __forceinline__ ulonglong2 ldcs2(const u64* p){
    ulonglong2 v;
    asm("ld.global.cs.v2.u64 {%0,%1},[%2];" : "=l"(v.x), "=l"(v.y) : "l"(p));
    return v;
}

// --------------------- k1: tensor product + |mid|^2 partials --------------
template<int TR,int P,int J,int N,int D1,int D2>
struct JL {
    static __device__ __forceinline__ void run(const float2 (&f1)[D1], const float2 (&f2)[D2],
                                               float& ar, float& ai){
        constexpr int L=kTL(TR), L1=kTL1(TR), L2=kTL2(TR);
        constexpr int M  = P - L;
        constexpr int M1 = ilo_c(L1,L2,M) + J;
        constexpr int M2 = M - M1;
        constexpr float v = (float)cgcoef(L1,M1,L2,M2,L,M);
        float2 a = f1[M1+L1];
        float2 b = f2[M2+L2];
        ar += v*(a.x*b.x - a.y*b.y);
        ai += v*(a.x*b.y + a.y*b.x);
        if constexpr (J+1 < N) JL<TR,P,J+1,N,D1,D2>::run(f1,f2,ar,ai);
    }
};

template<int TR,int P,int D1,int D2>
struct PL {
    static __device__ __forceinline__ void run(const float2 (&f1)[D1], const float2 (&f2)[D2],
                                               float2* op, float& nsq){
        constexpr int L  = kTL(TR);
        constexpr int N  = rown_c(kTL1(TR),kTL2(TR),P-L);
        constexpr long MLs = kMLf(L);
        float ar=0.f, ai=0.f;
        JL<TR,P,0,N,D1,D2>::run(f1,f2,ar,ai);
        __stcs(op + (long)P*MLs, make_float2(ar,ai));
        nsq += ar*ar + ai*ai;
        if constexpr (P+1 < 2*L+1) PL<TR,P+1,D1,D2>::run(f1,f2,op,nsq);
    }
};

template<int TR>
__device__ __forceinline__ void do_trip(const float* sF, int t, int s, int tid, int b0){
    constexpr int  L  = kTL(TR), L1 = kTL1(TR), L2 = kTL2(TR);
    constexpr int  D1 = 2*L1+1, D2 = 2*L2+1;
    constexpr int  ML = kMLf(L);
    constexpr long MB = kMidBase(L);
    const int cl = (TR - kTrip0(L))*256 + tid;
    float nsq = 0.f;
    for (int bs=0; bs<4; ++bs){
        const float2* fb = reinterpret_cast<const float2*>(sF + bs*512);
        float2 f1[D1], f2[D2];
        #pragma unroll
        for (int i=0;i<D1;++i) f1[i] = fb[kInOff(L1) + t*D1 + i];
        #pragma unroll
        for (int i=0;i<D2;++i) f2[i] = fb[kInOff(L2) + s*D2 + i];
        // layout: [b][p][c] — base at (b*DP)*ML + cl, p advances by ML
        float2* op = g_mid + MB + (long)(b0+bs)*(2*L+1)*ML + cl;
        PL<TR,0,D1,D2>::run(f1,f2,op,nsq);
    }
    g_part[(long)blockIdx.x*NCH + TR*256 + tid] = nsq;
}

template<int TR>
struct TripsAll {
    static __device__ __forceinline__ void run(const float* sF, int t, int s, int tid, int b0){
        do_trip<TR>(sF,t,s,tid,b0);
        if constexpr (TR+1 < 23) TripsAll<TR+1>::run(sF,t,s,tid,b0);
    }
};

__global__ void __launch_bounds__(256) k1_kernel(const float* __restrict__ act){
    __shared__ float sF[4*512];
    const int tid = threadIdx.x;
    const int b0  = blockIdx.x*4;
    const float4* src = reinterpret_cast<const float4*>(act + (long)b0*512);
    float4* dst = reinterpret_cast<float4*>(sF);
    for (int i=tid; i<512; i+=256) dst[i] = src[i];
    __syncthreads();
    TripsAll<0>::run(sF, tid>>4, tid&15, tid, b0);
}

// ------------- k2a: reduce partials -> inverse (new_std + eps) ------------
__global__ void k2a_kernel(const float* __restrict__ bn){
    int c = blockIdx.x*256 + threadIdx.x;
    if (c >= NCH) return;
    int l = (c<1024)?0:((c<2560)?1:((c<4352)?2:3));
    float s[8];
    #pragma unroll
    for (int j=0;j<8;++j) s[j]=0.f;
    for (int i=0;i<NBLK1;i+=8){
        #pragma unroll
        for (int j=0;j<8;++j) s[j] += g_part[(long)(i+j)*NCH + c];
    }
    float t = 0.f;
    #pragma unroll
    for (int j=0;j<8;++j) t += s[j];
    float bstd = sqrtf(t / (2048.0f * (float)(2*l+1)));
    g_scale[c] = 1.0f/(0.5f*(bn[c] + bstd) + 1e-5f);
}

// --------------- k2b: fold scale into W, duplicated lanes ------------------
__global__ void k2b_kernel(const float* __restrict__ W){
    int r = blockIdx.x*256 + threadIdx.x;
    if (r >= 94208) return;
    int l = (r<16384)?0:((r<40960)?1:((r<69632)?2:3));
    int rr = r - kWBase(l);
    int c  = rr % kMLf(l);
    float sc = g_scale[kSOff(l) + c];
    float wr = W[2*r]*sc, wi = W[2*r+1]*sc;
    g_wrr[r] = pk2(wr, wr);
    g_wii[r] = pk2(wi, wi);
}

// -------- k3: out[b,o,p] = sum_c Wsc[o,c]*mid[b,p,c]  (complex, f32x2) -----
// 512 blocks (4 b each); 256 threads = 8 cs x 8 og(2 o) x 4 bg(1 b)
template<int L>
__global__ void __launch_bounds__(256) k3_kernel(float* __restrict__ out){
    constexpr int  DP   = 2*L+1;
    constexpr int  ML   = kMLf(L);
    constexpr long MB   = kMidBase(L);
    constexpr int  WB   = kWBase(L);
    constexpr int  OROW = kInOff(L);

    const int tid = threadIdx.x;
    const int cs  = tid & 7;
    const int og  = (tid>>3) & 7;
    const int bg  = tid >> 6;
    const int o0  = og*2;
    const int b   = blockIdx.x*4 + bg;

    u64 a1[2][DP], a2[2][DP];
    #pragma unroll
    for (int oi=0;oi<2;++oi)
        #pragma unroll
        for (int p=0;p<DP;++p){ a1[oi][p]=0ULL; a2[oi][p]=0ULL; }

    const u64* wr0p = g_wrr + WB + (long)o0*ML;
    const u64* wi0p = g_wii + WB + (long)o0*ML;
    const u64* wr1p = wr0p + ML;
    const u64* wi1p = wi0p + ML;
    const u64* midp = reinterpret_cast<const u64*>(g_mid) + MB + (long)b*DP*ML;

    for (int c = cs*2; c < ML; c += 16){
        ulonglong2 wr0 = ldg2(wr0p + c);
        ulonglong2 wi0 = ldg2(wi0p + c);
        ulonglong2 wr1 = ldg2(wr1p + c);
        ulonglong2 wi1 = ldg2(wi1p + c);
        #pragma unroll
        for (int p=0;p<DP;++p){
            ulonglong2 m = ldcs2(midp + (long)p*ML + c);   // (c, c+1) complex
            a1[0][p] = fma2(wr0.x, m.x, a1[0][p]);
            a1[0][p] = fma2(wr0.y, m.y, a1[0][p]);
            a2[0][p] = fma2(wi0.x, m.x, a2[0][p]);
            a2[0][p] = fma2(wi0.y, m.y, a2[0][p]);
            a1[1][p] = fma2(wr1.x, m.x, a1[1][p]);
            a1[1][p] = fma2(wr1.y, m.y, a1[1][p]);
            a2[1][p] = fma2(wi1.x, m.x, a2[1][p]);
            a2[1][p] = fma2(wi1.y, m.y, a2[1][p]);
        }
    }

    // combine a1/a2 into complex result, then butterfly over cs (lane bits 0..2)
    #pragma unroll
    for (int oi=0;oi<2;++oi)
        #pragma unroll
        for (int p=0;p<DP;++p){
            float s1x,s1y,s2x,s2y;
            upk2(s1x,s1y,a1[oi][p]);
            upk2(s2x,s2y,a2[oi][p]);
            u64 v = pk2(s1x - s2y, s1y + s2x);
            v = add2(v, __shfl_xor_sync(0xffffffffu, v, 1));
            v = add2(v, __shfl_xor_sync(0xffffffffu, v, 2));
            v = add2(v, __shfl_xor_sync(0xffffffffu, v, 4));
            a1[oi][p] = v;
        }

    if (cs == 0){
        #pragma unroll
        for (int oi=0;oi<2;++oi)
            #pragma unroll
            for (int p=0;p<DP;++p){
                float x,y; upk2(x,y,a1[oi][p]);
                long row = (long)b*256 + OROW + (o0+oi)*DP + p;
                reinterpret_cast<float2*>(out)[row] = make_float2(x,y);
            }
    }
}

// --------------------------------- launch ---------------------------------
extern "C" void kernel_launch(void* const* d_in, const int* in_sizes, int n_in,
                              void* d_out, int out_size){
    const float* act = nullptr;
    const float* W   = nullptr;
    const float* bn  = nullptr;
    for (int i=0;i<n_in;++i){
        if      (in_sizes[i] == 1048576) act = (const float*)d_in[i];
        else if (in_sizes[i] == 188416)  W   = (const float*)d_in[i];
        else if (in_sizes[i] == 5888)    bn  = (const float*)d_in[i];
    }
    float* out = (float*)d_out;

    k1_kernel<<<512,256>>>(act);
    k2a_kernel<<<23,256>>>(bn);
    k2b_kernel<<<368,256>>>(W);
    k3_kernel<0><<<512,256>>>(out);
    k3_kernel<1><<<512,256>>>(out);
    k3_kernel<2><<<512,256>>>(out);
    k3_kernel<3><<<512,256>>>(out);
}

// round 11
// speedup vs baseline: 2.6925x; 1.9483x over previous
#include <cuda_runtime.h>
#include <math.h>

#define DEVHOST __host__ __device__
typedef unsigned long long u64;

// ------------------------- compile-time structure -------------------------
DEVHOST constexpr int kTL (int i){ const int a[23]={0,0,0,0, 1,1,1,1,1,1, 2,2,2,2,2,2,2, 3,3,3,3,3,3}; return a[i]; }
DEVHOST constexpr int kTL1(int i){ const int a[23]={0,1,2,3, 1,1,2,2,3,3, 1,2,2,2,3,3,3, 2,2,3,3,3,3}; return a[i]; }
DEVHOST constexpr int kTL2(int i){ const int a[23]={0,1,2,3, 0,1,1,2,2,3, 1,0,1,2,1,2,3, 1,2,0,1,2,3}; return a[i]; }

DEVHOST constexpr int imax2(int a,int b){ return a>b?a:b; }
DEVHOST constexpr int imin2(int a,int b){ return a<b?a:b; }
DEVHOST constexpr int ilo_c(int l1,int l2,int m){ return imax2(-l1, m-l2); }
DEVHOST constexpr int ihi_c(int l1,int l2,int m){ return imin2( l1, m+l2); }
DEVHOST constexpr int rown_c(int l1,int l2,int m){ return ihi_c(l1,l2,m)-ilo_c(l1,l2,m)+1; }

DEVHOST constexpr int kInOff(int l){ const int a[4]={0,16,64,144};        return a[l]; }
DEVHOST constexpr int kMLf  (int l){ const int a[4]={1024,1536,1792,1536}; return a[l]; }
DEVHOST constexpr int kTrip0(int l){ const int a[5]={0,4,10,17,23};        return a[l]; }
DEVHOST constexpr int kSOff (int l){ const int a[4]={0,1024,2560,4352};    return a[l]; }
DEVHOST constexpr int kWBase(int l){ const int a[4]={0,16384,40960,69632}; return a[l]; }

// ------------------- compile-time Clebsch-Gordan values -------------------
DEVHOST constexpr double dfact(int n){ double r=1.0; for(int i=2;i<=n;++i) r*=(double)i; return r; }
DEVHOST constexpr double csqrt(double x){
    double g = (x>1.0)?x:1.0;
    for(int i=0;i<64;++i) g = 0.5*(g + x/g);
    return g;
}
DEVHOST constexpr double cgcoef(int l1,int m1,int l2,int m2,int l,int m){
    double pre = csqrt((double)(2*l+1)*dfact(l1+l2-l)*dfact(l1-l2+l)*dfact(-l1+l2+l)/dfact(l1+l2+l+1));
    pre = pre * csqrt(dfact(l+m)*dfact(l-m)*dfact(l1-m1)*dfact(l1+m1)*dfact(l2-m2)*dfact(l2+m2));
    double s = 0.0;
    for(int k=0;k<=l1+l2-l;++k){
        int d0=k, d1=l1+l2-l-k, d2=l1-m1-k, d3=l2+m2-k, d4=l-l2+m1+k, d5=l-l1-m2+k;
        if(d0<0||d1<0||d2<0||d3<0||d4<0||d5<0) continue;
        double den = dfact(d0)*dfact(d1)*dfact(d2)*dfact(d3)*dfact(d4)*dfact(d5);
        s += ((k&1)? -1.0 : 1.0)/den;
    }
    return pre*s;
}

// ------------------------------ device scratch ----------------------------
static constexpr int NCH   = 5888;
static constexpr int NBLK1 = 512;

__device__ float g_part[(long)NBLK1 * NCH];
__device__ float g_scale[NCH];
__device__ u64   g_wrr[94208];
__device__ u64   g_wii[94208];

// -------------------------------- f32x2 ops -------------------------------
__device__ __forceinline__ u64 pk2(float lo, float hi){
    u64 r; asm("mov.b64 %0,{%1,%2};" : "=l"(r) : "f"(lo), "f"(hi)); return r;
}
__device__ __forceinline__ void upk2(float& lo, float& hi, u64 v){
    asm("mov.b64 {%0,%1},%2;" : "=f"(lo), "=f"(hi) : "l"(v));
}
__device__ __forceinline__ u64 fma2(u64 a, u64 b, u64 c){
    u64 d; asm("fma.rn.f32x2 %0,%1,%2,%3;" : "=l"(d) : "l"(a), "l"(b), "l"(c)); return d;
}
__device__ __forceinline__ u64 add2(u64 a, u64 b){
    u64 d; asm("add.rn.f32x2 %0,%1,%2;" : "=l"(d) : "l"(a), "l"(b)); return d;
}
__device__ __forceinline__ ulonglong2 ldg2(const u64* p){
    ulonglong2 v;
    asm("ld.global.nc.v2.u64 {%0,%1},[%2];" : "=l"(v.x), "=l"(v.y) : "l"(p));
    return v;
}

// ----------------------- shared TP inner template --------------------------
template<int TR,int P,int J,int N,int D1,int D2>
struct JL {
    static __device__ __forceinline__ void run(const float2 (&f1)[D1], const float2 (&f2)[D2],
                                               float& ar, float& ai){
        constexpr int L=kTL(TR), L1=kTL1(TR), L2=kTL2(TR);
        constexpr int M  = P - L;
        constexpr int M1 = ilo_c(L1,L2,M) + J;
        constexpr int M2 = M - M1;
        constexpr float v = (float)cgcoef(L1,M1,L2,M2,L,M);
        float2 a = f1[M1+L1];
        float2 b = f2[M2+L2];
        ar += v*(a.x*b.x - a.y*b.y);
        ai += v*(a.x*b.y + a.y*b.x);
        if constexpr (J+1 < N) JL<TR,P,J+1,N,D1,D2>::run(f1,f2,ar,ai);
    }
};

// nsq-only variant (k1')
template<int TR,int P,int D1,int D2>
struct PLn {
    static __device__ __forceinline__ void run(const float2 (&f1)[D1], const float2 (&f2)[D2], float& nsq){
        constexpr int L = kTL(TR);
        constexpr int N = rown_c(kTL1(TR),kTL2(TR),P-L);
        float ar=0.f, ai=0.f;
        JL<TR,P,0,N,D1,D2>::run(f1,f2,ar,ai);
        nsq += ar*ar + ai*ai;
        if constexpr (P+1 < 2*L+1) PLn<TR,P+1,D1,D2>::run(f1,f2,nsq);
    }
};

// smem-store variant (k3f phase A): stride 256 between p planes
template<int TR,int P,int D1,int D2>
struct PLs {
    static __device__ __forceinline__ void run(const float2 (&f1)[D1], const float2 (&f2)[D2], float2* op){
        constexpr int L = kTL(TR);
        constexpr int N = rown_c(kTL1(TR),kTL2(TR),P-L);
        float ar=0.f, ai=0.f;
        JL<TR,P,0,N,D1,D2>::run(f1,f2,ar,ai);
        op[P*256] = make_float2(ar,ai);
        if constexpr (P+1 < 2*L+1) PLs<TR,P+1,D1,D2>::run(f1,f2,op);
    }
};

// --------------------- k1': TP -> |mid|^2 partials only --------------------
template<int TR>
__device__ __forceinline__ void do_tripn(const float* sF, int t, int s, int tid){
    constexpr int L1 = kTL1(TR), L2 = kTL2(TR);
    constexpr int D1 = 2*L1+1, D2 = 2*L2+1;
    float nsq = 0.f;
    for (int bs=0; bs<4; ++bs){
        const float2* fb = reinterpret_cast<const float2*>(sF + bs*512);
        float2 f1[D1], f2[D2];
        #pragma unroll
        for (int i=0;i<D1;++i) f1[i] = fb[kInOff(L1) + t*D1 + i];
        #pragma unroll
        for (int i=0;i<D2;++i) f2[i] = fb[kInOff(L2) + s*D2 + i];
        PLn<TR,0,D1,D2>::run(f1,f2,nsq);
    }
    g_part[(long)blockIdx.x*NCH + TR*256 + tid] = nsq;
}

template<int TR>
struct TripsN {
    static __device__ __forceinline__ void run(const float* sF, int t, int s, int tid){
        do_tripn<TR>(sF,t,s,tid);
        if constexpr (TR+1 < 23) TripsN<TR+1>::run(sF,t,s,tid);
    }
};

__global__ void __launch_bounds__(256) k1_kernel(const float* __restrict__ act){
    __shared__ float sF[4*512];
    const int tid = threadIdx.x;
    const int b0  = blockIdx.x*4;
    const float4* src = reinterpret_cast<const float4*>(act + (long)b0*512);
    float4* dst = reinterpret_cast<float4*>(sF);
    for (int i=tid; i<512; i+=256) dst[i] = src[i];
    __syncthreads();
    TripsN<0>::run(sF, tid>>4, tid&15, tid);
}

// ------------- k2a: reduce partials -> inverse (new_std + eps) ------------
__global__ void k2a_kernel(const float* __restrict__ bn){
    int c = blockIdx.x*256 + threadIdx.x;
    if (c >= NCH) return;
    int l = (c<1024)?0:((c<2560)?1:((c<4352)?2:3));
    float s[8];
    #pragma unroll
    for (int j=0;j<8;++j) s[j]=0.f;
    for (int i=0;i<NBLK1;i+=8){
        #pragma unroll
        for (int j=0;j<8;++j) s[j] += g_part[(long)(i+j)*NCH + c];
    }
    float t = 0.f;
    #pragma unroll
    for (int j=0;j<8;++j) t += s[j];
    float bstd = sqrtf(t / (2048.0f * (float)(2*l+1)));
    g_scale[c] = 1.0f/(0.5f*(bn[c] + bstd) + 1e-5f);
}

// --------------- k2b: fold scale into W, duplicated lanes ------------------
__global__ void k2b_kernel(const float* __restrict__ W){
    int r = blockIdx.x*256 + threadIdx.x;
    if (r >= 94208) return;
    int l = (r<16384)?0:((r<40960)?1:((r<69632)?2:3));
    int rr = r - kWBase(l);
    int c  = rr % kMLf(l);
    float sc = g_scale[kSOff(l) + c];
    float wr = W[2*r]*sc, wi = W[2*r+1]*sc;
    g_wrr[r] = pk2(wr, wr);
    g_wii[r] = pk2(wi, wi);
}

// ---------------- k3f: fused TP-recompute + complex GEMM -------------------
// Block: 8 batches x one l. Per triple: phase A (TP -> smem, 256 chans x 8 b),
// phase B (GEMM from smem, acc in regs). Threads: cs(8) x og(4, 4 o each) x bi(8).
static constexpr int SMEM_MID_BYTES = 8*7*256*8;   // 114688
static constexpr int SMEM_ACT_OFF   = SMEM_MID_BYTES;
static constexpr int SMEM_TOTAL     = SMEM_MID_BYTES + 8*512*4; // 131072

template<int L,int TR>
__device__ __forceinline__ void phaseA(const float2* actsm, float2* smid, int tid){
    constexpr int L1 = kTL1(TR), L2 = kTL2(TR);
    constexpr int D1 = 2*L1+1, D2 = 2*L2+1;
    constexpr int DP = 2*L+1;
    const int t = tid>>4, s = tid&15;
    #pragma unroll 2
    for (int b=0;b<8;++b){
        const float2* fb = actsm + b*256;
        float2 f1[D1], f2[D2];
        #pragma unroll
        for (int i=0;i<D1;++i) f1[i] = fb[kInOff(L1) + t*D1 + i];
        #pragma unroll
        for (int i=0;i<D2;++i) f2[i] = fb[kInOff(L2) + s*D2 + i];
        PLs<TR,0,D1,D2>::run(f1,f2, smid + b*(DP*256) + tid);
    }
}

template<int L,int TR>
__device__ __forceinline__ void phaseB(const u64* smid,
                                       u64 (&a1)[4][2*L+1], u64 (&a2)[4][2*L+1],
                                       int cs, int o0, int bi){
    constexpr int DP = 2*L+1;
    constexpr int ML = kMLf(L);
    constexpr int WB = kWBase(L);
    constexpr int TB = (TR - kTrip0(L))*256;
    const u64* mbase = smid + bi*(DP*256);
    #pragma unroll 2
    for (int it=0; it<16; ++it){
        const int c = it*16 + cs*2;
        ulonglong2 wr[4], wi[4];
        #pragma unroll
        for (int oi=0;oi<4;++oi){
            wr[oi] = ldg2(g_wrr + WB + (o0+oi)*ML + TB + c);
            wi[oi] = ldg2(g_wii + WB + (o0+oi)*ML + TB + c);
        }
        #pragma unroll
        for (int p=0;p<DP;++p){
            ulonglong2 m = *reinterpret_cast<const ulonglong2*>(mbase + p*256 + c);
            #pragma unroll
            for (int oi=0;oi<4;++oi){
                a1[oi][p] = fma2(wr[oi].x, m.x, a1[oi][p]);
                a1[oi][p] = fma2(wr[oi].y, m.y, a1[oi][p]);
                a2[oi][p] = fma2(wi[oi].x, m.x, a2[oi][p]);
                a2[oi][p] = fma2(wi[oi].y, m.y, a2[oi][p]);
            }
        }
    }
}

template<int L,int TR,int TREND>
struct TripF {
    static __device__ __forceinline__ void run(const float2* actsm, float2* smidf, const u64* smidu,
                                               u64 (&a1)[4][2*L+1], u64 (&a2)[4][2*L+1],
                                               int tid, int cs, int o0, int bi){
        phaseA<L,TR>(actsm, smidf, tid);
        __syncthreads();
        phaseB<L,TR>(smidu, a1, a2, cs, o0, bi);
        __syncthreads();
        if constexpr (TR+1 < TREND)
            TripF<L,TR+1,TREND>::run(actsm,smidf,smidu,a1,a2,tid,cs,o0,bi);
    }
};

template<int L>
__device__ __forceinline__ void k3body(const float* __restrict__ act, float* __restrict__ out,
                                       int bg, char* sm){
    constexpr int DP   = 2*L+1;
    constexpr int OROW = kInOff(L);
    u64*    smidu = reinterpret_cast<u64*>(sm);
    float2* smidf = reinterpret_cast<float2*>(sm);
    float2* actsm = reinterpret_cast<float2*>(sm + SMEM_ACT_OFF);

    const int tid = threadIdx.x;
    const int b0  = bg*8;

    // load 8 batches of activations into smem
    const float4* src = reinterpret_cast<const float4*>(act + (long)b0*512);
    float4* adst = reinterpret_cast<float4*>(actsm);
    for (int i=tid;i<1024;i+=256) adst[i] = src[i];
    __syncthreads();

    const int cs = tid & 7;
    const int og = (tid>>3) & 3;
    const int bi = tid >> 5;
    const int o0 = og*4;

    u64 a1[4][DP], a2[4][DP];
    #pragma unroll
    for (int oi=0;oi<4;++oi)
        #pragma unroll
        for (int p=0;p<DP;++p){ a1[oi][p]=0ULL; a2[oi][p]=0ULL; }

    TripF<L, kTrip0(L), kTrip0(L+1)>::run(actsm, smidf, smidu, a1, a2, tid, cs, o0, bi);

    // combine (a1,a2) -> complex, deterministic butterfly over cs (lane bits 0..2)
    #pragma unroll
    for (int oi=0;oi<4;++oi)
        #pragma unroll
        for (int p=0;p<DP;++p){
            float s1x,s1y,s2x,s2y;
            upk2(s1x,s1y,a1[oi][p]);
            upk2(s2x,s2y,a2[oi][p]);
            u64 v = pk2(s1x - s2y, s1y + s2x);
            v = add2(v, __shfl_xor_sync(0xffffffffu, v, 1));
            v = add2(v, __shfl_xor_sync(0xffffffffu, v, 2));
            v = add2(v, __shfl_xor_sync(0xffffffffu, v, 4));
            a1[oi][p] = v;
        }

    if (cs == 0){
        #pragma unroll
        for (int oi=0;oi<4;++oi)
            #pragma unroll
            for (int p=0;p<DP;++p){
                float x,y; upk2(x,y,a1[oi][p]);
                long row = (long)(b0+bi)*256 + OROW + (o0+oi)*DP + p;
                reinterpret_cast<float2*>(out)[row] = make_float2(x,y);
            }
    }
}

__global__ void __launch_bounds__(256,1) k3f_kernel(const float* __restrict__ act,
                                                    float* __restrict__ out){
    extern __shared__ char sm[];
    const int bid = blockIdx.x;
    const int li  = bid >> 8;       // 0..3, longest l first
    const int bg  = bid & 255;
    switch (li){
        case 0: k3body<3>(act,out,bg,sm); break;
        case 1: k3body<2>(act,out,bg,sm); break;
        case 2: k3body<1>(act,out,bg,sm); break;
        default: k3body<0>(act,out,bg,sm); break;
    }
}

// --------------------------------- launch ---------------------------------
extern "C" void kernel_launch(void* const* d_in, const int* in_sizes, int n_in,
                              void* d_out, int out_size){
    const float* act = nullptr;
    const float* W   = nullptr;
    const float* bn  = nullptr;
    for (int i=0;i<n_in;++i){
        if      (in_sizes[i] == 1048576) act = (const float*)d_in[i];
        else if (in_sizes[i] == 188416)  W   = (const float*)d_in[i];
        else if (in_sizes[i] == 5888)    bn  = (const float*)d_in[i];
    }
    float* out = (float*)d_out;

    static bool attr_set = false;
    if (!attr_set){
        cudaFuncSetAttribute(k3f_kernel, cudaFuncAttributeMaxDynamicSharedMemorySize, SMEM_TOTAL);
        attr_set = true;
    }

    k1_kernel<<<512,256>>>(act);
    k2a_kernel<<<23,256>>>(bn);
    k2b_kernel<<<368,256>>>(W);
    k3f_kernel<<<1024,256,SMEM_TOTAL>>>(act, out);
}

// round 12
// speedup vs baseline: 2.8262x; 1.0496x over previous
#include <cuda_runtime.h>
#include <math.h>

#define DEVHOST __host__ __device__
typedef unsigned long long u64;

// ------------------------- compile-time structure -------------------------
DEVHOST constexpr int kTL (int i){ const int a[23]={0,0,0,0, 1,1,1,1,1,1, 2,2,2,2,2,2,2, 3,3,3,3,3,3}; return a[i]; }
DEVHOST constexpr int kTL1(int i){ const int a[23]={0,1,2,3, 1,1,2,2,3,3, 1,2,2,2,3,3,3, 2,2,3,3,3,3}; return a[i]; }
DEVHOST constexpr int kTL2(int i){ const int a[23]={0,1,2,3, 0,1,1,2,2,3, 1,0,1,2,1,2,3, 1,2,0,1,2,3}; return a[i]; }

DEVHOST constexpr int imax2(int a,int b){ return a>b?a:b; }
DEVHOST constexpr int imin2(int a,int b){ return a<b?a:b; }
DEVHOST constexpr int ilo_c(int l1,int l2,int m){ return imax2(-l1, m-l2); }
DEVHOST constexpr int ihi_c(int l1,int l2,int m){ return imin2( l1, m+l2); }
DEVHOST constexpr int rown_c(int l1,int l2,int m){ return ihi_c(l1,l2,m)-ilo_c(l1,l2,m)+1; }

DEVHOST constexpr int kInOff(int l){ const int a[4]={0,16,64,144};        return a[l]; }
DEVHOST constexpr int kMLf  (int l){ const int a[4]={1024,1536,1792,1536}; return a[l]; }
DEVHOST constexpr int kTrip0(int l){ const int a[5]={0,4,10,17,23};        return a[l]; }
DEVHOST constexpr int kSOff (int l){ const int a[4]={0,1024,2560,4352};    return a[l]; }
DEVHOST constexpr int kWBase(int l){ const int a[4]={0,16384,40960,69632}; return a[l]; }

// ------------------- compile-time Clebsch-Gordan values -------------------
DEVHOST constexpr double dfact(int n){ double r=1.0; for(int i=2;i<=n;++i) r*=(double)i; return r; }
DEVHOST constexpr double csqrt(double x){
    double g = (x>1.0)?x:1.0;
    for(int i=0;i<64;++i) g = 0.5*(g + x/g);
    return g;
}
DEVHOST constexpr double cgcoef(int l1,int m1,int l2,int m2,int l,int m){
    double pre = csqrt((double)(2*l+1)*dfact(l1+l2-l)*dfact(l1-l2+l)*dfact(-l1+l2+l)/dfact(l1+l2+l+1));
    pre = pre * csqrt(dfact(l+m)*dfact(l-m)*dfact(l1-m1)*dfact(l1+m1)*dfact(l2-m2)*dfact(l2+m2));
    double s = 0.0;
    for(int k=0;k<=l1+l2-l;++k){
        int d0=k, d1=l1+l2-l-k, d2=l1-m1-k, d3=l2+m2-k, d4=l-l2+m1+k, d5=l-l1-m2+k;
        if(d0<0||d1<0||d2<0||d3<0||d4<0||d5<0) continue;
        double den = dfact(d0)*dfact(d1)*dfact(d2)*dfact(d3)*dfact(d4)*dfact(d5);
        s += ((k&1)? -1.0 : 1.0)/den;
    }
    return pre*s;
}

// ------------------------------ device scratch ----------------------------
static constexpr int NCH   = 5888;
static constexpr int NBLK1 = 512;

__device__ float g_part[(long)NBLK1 * NCH];
__device__ float g_scale[NCH];
__device__ u64   g_wrr[94208];
__device__ u64   g_wii[94208];

// -------------------------------- f32x2 ops -------------------------------
__device__ __forceinline__ u64 pk2(float lo, float hi){
    u64 r; asm("mov.b64 %0,{%1,%2};" : "=l"(r) : "f"(lo), "f"(hi)); return r;
}
__device__ __forceinline__ void upk2(float& lo, float& hi, u64 v){
    asm("mov.b64 {%0,%1},%2;" : "=f"(lo), "=f"(hi) : "l"(v));
}
__device__ __forceinline__ u64 fma2(u64 a, u64 b, u64 c){
    u64 d; asm("fma.rn.f32x2 %0,%1,%2,%3;" : "=l"(d) : "l"(a), "l"(b), "l"(c)); return d;
}
__device__ __forceinline__ u64 add2(u64 a, u64 b){
    u64 d; asm("add.rn.f32x2 %0,%1,%2;" : "=l"(d) : "l"(a), "l"(b)); return d;
}
__device__ __forceinline__ ulonglong2 ldg2(const u64* p){
    ulonglong2 v;
    asm("ld.global.nc.v2.u64 {%0,%1},[%2];" : "=l"(v.x), "=l"(v.y) : "l"(p));
    return v;
}

// ----------------------- shared TP inner template --------------------------
template<int TR,int P,int J,int N,int D1,int D2>
struct JL {
    static __device__ __forceinline__ void run(const float2 (&f1)[D1], const float2 (&f2)[D2],
                                               float& ar, float& ai){
        constexpr int L=kTL(TR), L1=kTL1(TR), L2=kTL2(TR);
        constexpr int M  = P - L;
        constexpr int M1 = ilo_c(L1,L2,M) + J;
        constexpr int M2 = M - M1;
        constexpr float v = (float)cgcoef(L1,M1,L2,M2,L,M);
        float2 a = f1[M1+L1];
        float2 b = f2[M2+L2];
        ar += v*(a.x*b.x - a.y*b.y);
        ai += v*(a.x*b.y + a.y*b.x);
        if constexpr (J+1 < N) JL<TR,P,J+1,N,D1,D2>::run(f1,f2,ar,ai);
    }
};

// nsq-only variant (k1')
template<int TR,int P,int D1,int D2>
struct PLn {
    static __device__ __forceinline__ void run(const float2 (&f1)[D1], const float2 (&f2)[D2], float& nsq){
        constexpr int L = kTL(TR);
        constexpr int N = rown_c(kTL1(TR),kTL2(TR),P-L);
        float ar=0.f, ai=0.f;
        JL<TR,P,0,N,D1,D2>::run(f1,f2,ar,ai);
        nsq += ar*ar + ai*ai;
        if constexpr (P+1 < 2*L+1) PLn<TR,P+1,D1,D2>::run(f1,f2,nsq);
    }
};

// smem-store variant (k3f phase A): stride 256 between p planes
template<int TR,int P,int D1,int D2>
struct PLs {
    static __device__ __forceinline__ void run(const float2 (&f1)[D1], const float2 (&f2)[D2], float2* op){
        constexpr int L = kTL(TR);
        constexpr int N = rown_c(kTL1(TR),kTL2(TR),P-L);
        float ar=0.f, ai=0.f;
        JL<TR,P,0,N,D1,D2>::run(f1,f2,ar,ai);
        op[P*256] = make_float2(ar,ai);
        if constexpr (P+1 < 2*L+1) PLs<TR,P+1,D1,D2>::run(f1,f2,op);
    }
};

// --------------------- k1': TP -> |mid|^2 partials only --------------------
template<int TR>
__device__ __forceinline__ void do_tripn(const float* sF, int t, int s, int tid){
    constexpr int L1 = kTL1(TR), L2 = kTL2(TR);
    constexpr int D1 = 2*L1+1, D2 = 2*L2+1;
    float nsq = 0.f;
    for (int bs=0; bs<4; ++bs){
        const float2* fb = reinterpret_cast<const float2*>(sF + bs*512);
        float2 f1[D1], f2[D2];
        #pragma unroll
        for (int i=0;i<D1;++i) f1[i] = fb[kInOff(L1) + t*D1 + i];
        #pragma unroll
        for (int i=0;i<D2;++i) f2[i] = fb[kInOff(L2) + s*D2 + i];
        PLn<TR,0,D1,D2>::run(f1,f2,nsq);
    }
    g_part[(long)blockIdx.x*NCH + TR*256 + tid] = nsq;
}

template<int TR>
struct TripsN {
    static __device__ __forceinline__ void run(const float* sF, int t, int s, int tid){
        do_tripn<TR>(sF,t,s,tid);
        if constexpr (TR+1 < 23) TripsN<TR+1>::run(sF,t,s,tid);
    }
};

__global__ void __launch_bounds__(256) k1_kernel(const float* __restrict__ act){
    __shared__ float sF[4*512];
    const int tid = threadIdx.x;
    const int b0  = blockIdx.x*4;
    const float4* src = reinterpret_cast<const float4*>(act + (long)b0*512);
    float4* dst = reinterpret_cast<float4*>(sF);
    for (int i=tid; i<512; i+=256) dst[i] = src[i];
    __syncthreads();
    TripsN<0>::run(sF, tid>>4, tid&15, tid);
}

// ------------- k2a: reduce partials -> inverse (new_std + eps) ------------
__global__ void k2a_kernel(const float* __restrict__ bn){
    int c = blockIdx.x*256 + threadIdx.x;
    if (c >= NCH) return;
    int l = (c<1024)?0:((c<2560)?1:((c<4352)?2:3));
    float s[8];
    #pragma unroll
    for (int j=0;j<8;++j) s[j]=0.f;
    for (int i=0;i<NBLK1;i+=8){
        #pragma unroll
        for (int j=0;j<8;++j) s[j] += g_part[(long)(i+j)*NCH + c];
    }
    float t = 0.f;
    #pragma unroll
    for (int j=0;j<8;++j) t += s[j];
    float bstd = sqrtf(t / (2048.0f * (float)(2*l+1)));
    g_scale[c] = 1.0f/(0.5f*(bn[c] + bstd) + 1e-5f);
}

// --------------- k2b: fold scale into W, duplicated lanes ------------------
__global__ void k2b_kernel(const float* __restrict__ W){
    int r = blockIdx.x*256 + threadIdx.x;
    if (r >= 94208) return;
    int l = (r<16384)?0:((r<40960)?1:((r<69632)?2:3));
    int rr = r - kWBase(l);
    int c  = rr % kMLf(l);
    float sc = g_scale[kSOff(l) + c];
    float wr = W[2*r]*sc, wi = W[2*r+1]*sc;
    g_wrr[r] = pk2(wr, wr);
    g_wii[r] = pk2(wi, wi);
}

// ---------------- k3f: fused TP-recompute + complex GEMM -------------------
// Block: 512 threads, 8 batches x one l. Per triple:
//   phase A: TP -> smem (two 256-thread halves, 4 batches each)
//   phase B: GEMM from smem; threads = cs(8) x og(8, 2 o each) x bi(8)
static constexpr int SMEM_MID_BYTES = 8*7*256*8;   // 114688
static constexpr int SMEM_ACT_OFF   = SMEM_MID_BYTES;
static constexpr int SMEM_TOTAL     = SMEM_MID_BYTES + 8*512*4; // 131072

template<int L,int TR>
__device__ __forceinline__ void phaseA(const float2* actsm, float2* smid, int tid){
    constexpr int L1 = kTL1(TR), L2 = kTL2(TR);
    constexpr int D1 = 2*L1+1, D2 = 2*L2+1;
    constexpr int DP = 2*L+1;
    const int ch   = tid & 255;
    const int t    = ch >> 4, s = ch & 15;
    const int bset = (tid >> 8) * 4;      // 0 or 4
    #pragma unroll 2
    for (int bs=0;bs<4;++bs){
        const int b = bset + bs;
        const float2* fb = actsm + b*256;
        float2 f1[D1], f2[D2];
        #pragma unroll
        for (int i=0;i<D1;++i) f1[i] = fb[kInOff(L1) + t*D1 + i];
        #pragma unroll
        for (int i=0;i<D2;++i) f2[i] = fb[kInOff(L2) + s*D2 + i];
        PLs<TR,0,D1,D2>::run(f1,f2, smid + b*(DP*256) + ch);
    }
}

template<int L,int TR>
__device__ __forceinline__ void phaseB(const u64* smid,
                                       u64 (&a1)[2][2*L+1], u64 (&a2)[2][2*L+1],
                                       int cs, int o0, int bi){
    constexpr int DP = 2*L+1;
    constexpr int ML = kMLf(L);
    constexpr int WB = kWBase(L);
    constexpr int TB = (TR - kTrip0(L))*256;
    const u64* mbase = smid + bi*(DP*256);
    #pragma unroll 2
    for (int it=0; it<16; ++it){
        const int c = it*16 + cs*2;
        ulonglong2 wr[2], wi[2];
        #pragma unroll
        for (int oi=0;oi<2;++oi){
            wr[oi] = ldg2(g_wrr + WB + (o0+oi)*ML + TB + c);
            wi[oi] = ldg2(g_wii + WB + (o0+oi)*ML + TB + c);
        }
        #pragma unroll
        for (int p=0;p<DP;++p){
            ulonglong2 m = *reinterpret_cast<const ulonglong2*>(mbase + p*256 + c);
            #pragma unroll
            for (int oi=0;oi<2;++oi){
                a1[oi][p] = fma2(wr[oi].x, m.x, a1[oi][p]);
                a1[oi][p] = fma2(wr[oi].y, m.y, a1[oi][p]);
                a2[oi][p] = fma2(wi[oi].x, m.x, a2[oi][p]);
                a2[oi][p] = fma2(wi[oi].y, m.y, a2[oi][p]);
            }
        }
    }
}

template<int L,int TR,int TREND>
struct TripF {
    static __device__ __forceinline__ void run(const float2* actsm, float2* smidf, const u64* smidu,
                                               u64 (&a1)[2][2*L+1], u64 (&a2)[2][2*L+1],
                                               int tid, int cs, int o0, int bi){
        phaseA<L,TR>(actsm, smidf, tid);
        __syncthreads();
        phaseB<L,TR>(smidu, a1, a2, cs, o0, bi);
        __syncthreads();
        if constexpr (TR+1 < TREND)
            TripF<L,TR+1,TREND>::run(actsm,smidf,smidu,a1,a2,tid,cs,o0,bi);
    }
};

template<int L>
__device__ __forceinline__ void k3body(const float* __restrict__ act, float* __restrict__ out,
                                       int bg, char* sm){
    constexpr int DP   = 2*L+1;
    constexpr int OROW = kInOff(L);
    u64*    smidu = reinterpret_cast<u64*>(sm);
    float2* smidf = reinterpret_cast<float2*>(sm);
    float2* actsm = reinterpret_cast<float2*>(sm + SMEM_ACT_OFF);

    const int tid = threadIdx.x;
    const int b0  = bg*8;

    // load 8 batches of activations into smem
    const float4* src = reinterpret_cast<const float4*>(act + (long)b0*512);
    float4* adst = reinterpret_cast<float4*>(actsm);
    for (int i=tid;i<1024;i+=512) adst[i] = src[i];
    __syncthreads();

    const int cs = tid & 7;
    const int og = (tid>>3) & 7;
    const int bi = tid >> 6;
    const int o0 = og*2;

    u64 a1[2][DP], a2[2][DP];
    #pragma unroll
    for (int oi=0;oi<2;++oi)
        #pragma unroll
        for (int p=0;p<DP;++p){ a1[oi][p]=0ULL; a2[oi][p]=0ULL; }

    TripF<L, kTrip0(L), kTrip0(L+1)>::run(actsm, smidf, smidu, a1, a2, tid, cs, o0, bi);

    // combine (a1,a2) -> complex, deterministic butterfly over cs (lane bits 0..2)
    #pragma unroll
    for (int oi=0;oi<2;++oi)
        #pragma unroll
        for (int p=0;p<DP;++p){
            float s1x,s1y,s2x,s2y;
            upk2(s1x,s1y,a1[oi][p]);
            upk2(s2x,s2y,a2[oi][p]);
            u64 v = pk2(s1x - s2y, s1y + s2x);
            v = add2(v, __shfl_xor_sync(0xffffffffu, v, 1));
            v = add2(v, __shfl_xor_sync(0xffffffffu, v, 2));
            v = add2(v, __shfl_xor_sync(0xffffffffu, v, 4));
            a1[oi][p] = v;
        }

    if (cs == 0){
        #pragma unroll
        for (int oi=0;oi<2;++oi)
            #pragma unroll
            for (int p=0;p<DP;++p){
                float x,y; upk2(x,y,a1[oi][p]);
                long row = (long)(b0+bi)*256 + OROW + (o0+oi)*DP + p;
                reinterpret_cast<float2*>(out)[row] = make_float2(x,y);
            }
    }
}

__global__ void __launch_bounds__(512,1) k3f_kernel(const float* __restrict__ act,
                                                    float* __restrict__ out){
    extern __shared__ char sm[];
    const int bid = blockIdx.x;
    const int li  = bid >> 8;       // 0..3, longest l first
    const int bg  = bid & 255;
    switch (li){
        case 0: k3body<3>(act,out,bg,sm); break;
        case 1: k3body<2>(act,out,bg,sm); break;
        case 2: k3body<1>(act,out,bg,sm); break;
        default: k3body<0>(act,out,bg,sm); break;
    }
}

// --------------------------------- launch ---------------------------------
extern "C" void kernel_launch(void* const* d_in, const int* in_sizes, int n_in,
                              void* d_out, int out_size){
    const float* act = nullptr;
    const float* W   = nullptr;
    const float* bn  = nullptr;
    for (int i=0;i<n_in;++i){
        if      (in_sizes[i] == 1048576) act = (const float*)d_in[i];
        else if (in_sizes[i] == 188416)  W   = (const float*)d_in[i];
        else if (in_sizes[i] == 5888)    bn  = (const float*)d_in[i];
    }
    float* out = (float*)d_out;

    static bool attr_set = false;
    if (!attr_set){
        cudaFuncSetAttribute(k3f_kernel, cudaFuncAttributeMaxDynamicSharedMemorySize, SMEM_TOTAL);
        attr_set = true;
    }

    k1_kernel<<<512,256>>>(act);
    k2a_kernel<<<23,256>>>(bn);
    k2b_kernel<<<368,256>>>(W);
    k3f_kernel<<<1024,512,SMEM_TOTAL>>>(act, out);
}